// round 9
// baseline (speedup 1.0000x reference)
#include <cuda_runtime.h>

// rate_RNN_mante: T=1000 sequential steps, B=64, IN=4, H=512, OUT=3.
// Recurrent weight Wr = (l*pin) @ pout^T is rank-2 -> per step only two
// H-wide reductions (s0,s1) are on the critical path. One CTA per batch,
// 4 warps x 32 lanes x 4 hidden units per thread.
//
// Reduction: per-thread FMA tree (4 units) -> 4 shfl_down rounds (2 partials
// per warp) -> smem float2 partials, ONE __syncthreads (double-buffered) ->
// float4 broadcast LDS + depth-3 add tree. Output reductions (Wout @ tanh(mem))
// stop at the partial stage and are streamed to global scratch; a tiny second
// kernel finalizes y. tanh = 1 - 2/(e^{2x}+1) via MUFU EX2+RCP.

#define TSTEPS 1000
#define BATCH  64
#define HID    512
#define OUTDIM 3
#define NTHR   128          // 4 warps
#define UPT    4            // hidden units per thread

// y partial scratch: [B][T][OUT][8 partials]  (24.6 MB, static device array)
__device__ float g_ypart[BATCH * TSTEPS * OUTDIM * 8];

__device__ __forceinline__ float fast_tanh(float x) {
    // tanh(x) = 1 - 2/(exp(2x)+1); EX2/RCP approx errs ~1e-7 absolute.
    float e, r;
    asm("ex2.approx.f32 %0, %1;" : "=f"(e) : "f"(x * 2.88539008177792681472f)); // 2*log2(e)
    asm("rcp.approx.f32 %0, %1;" : "=f"(r) : "f"(e + 1.0f));
    return fmaf(-2.0f, r, 1.0f);
}

__global__ __launch_bounds__(NTHR, 1)
void rate_rnn_scan_kernel(const float* __restrict__ x,
                          const float* __restrict__ Win,
                          const float* __restrict__ Wout,
                          const float* __restrict__ pin,
                          const float* __restrict__ pout,
                          const float* __restrict__ l)
{
    const int b    = blockIdx.x;
    const int tid  = threadIdx.x;
    const int lane = tid & 31;
    const int wid  = tid >> 5;
    const int half = lane >> 4;            // 0: lanes 0-15, 1: lanes 16-31
    const int slot = wid * 2 + half;       // 8 partial slots

    __shared__ float4 xs[TSTEPS];                       // staged input column (16 KB)
    __shared__ __align__(16) float2 sp[2][8];           // double-buffered s partials

    // Stage this batch's x column once (x is [T,B,4,1] -> float4 rows).
    const float4* x4 = reinterpret_cast<const float4*>(x);
    for (int t = tid; t < TSTEPS; t += NTHR)
        xs[t] = x4[t * BATCH + b];

    const float lm = 0.90483741803595952735f;   // exp(-dt/taum) = exp(-0.1)
    const float om = 1.0f - lm;
    const float l0 = l[0], l1 = l[1];

    // Per-thread weights for units h = 4*tid + k. Fold om into Win and pin*l.
    float4 wi[UPT];
    float  pi0[UPT], pi1[UPT], po0[UPT], po1[UPT];
    float  wo0[UPT], wo1[UPT], wo2[UPT];
    float  mem[UPT];
#pragma unroll
    for (int k = 0; k < UPT; ++k) {
        int h = tid * UPT + k;
        float4 w = reinterpret_cast<const float4*>(Win)[h];
        wi[k] = make_float4(w.x * om, w.y * om, w.z * om, w.w * om);
        pi0[k] = pin[h * 2 + 0] * l0 * om;
        pi1[k] = pin[h * 2 + 1] * l1 * om;
        po0[k] = pout[h * 2 + 0];
        po1[k] = pout[h * 2 + 1];
        wo0[k] = Wout[h];
        wo1[k] = Wout[HID + h];
        wo2[k] = Wout[2 * HID + h];
        mem[k] = 0.0f;
    }

    float s0 = 0.0f, s1 = 0.0f;   // pout^T tanh(mem_{t-1}); zero at t=0
    int buf = 0;

    float* ypbase = g_ypart + ((size_t)b * TSTEPS) * (OUTDIM * 8) + slot;

    __syncthreads();   // xs staged

    for (int t = 0; t < TSTEPS; ++t) {
        float4 xt = xs[t];
        float r[UPT];

        // acc = lm*mem + om*Win.x_t   (independent of s -> off critical path)
        float acc[UPT];
#pragma unroll
        for (int k = 0; k < UPT; ++k) {
            float iin = fmaf(wi[k].w, xt.w, fmaf(wi[k].z, xt.z,
                        fmaf(wi[k].y, xt.y, wi[k].x * xt.x)));
            acc[k] = fmaf(lm, mem[k], iin);
        }
        // Critical chain: s -> mem -> tanh
#pragma unroll
        for (int k = 0; k < UPT; ++k) {
            float m = fmaf(pi1[k], s1, fmaf(pi0[k], s0, acc[k]));
            mem[k] = m;
            r[k] = fast_tanh(m);
        }

        // Per-thread FMA trees over the 4 units (depth ~3 FMA).
        float v  = (fmaf(po0[1], r[1], po0[0] * r[0]) + fmaf(po0[3], r[3], po0[2] * r[2]));
        float u  = (fmaf(po1[1], r[1], po1[0] * r[0]) + fmaf(po1[3], r[3], po1[2] * r[2]));
        float y0 = (fmaf(wo0[1], r[1], wo0[0] * r[0]) + fmaf(wo0[3], r[3], wo0[2] * r[2]));
        float y1 = (fmaf(wo1[1], r[1], wo1[0] * r[0]) + fmaf(wo1[3], r[3], wo1[2] * r[2]));
        float y2 = (fmaf(wo2[1], r[1], wo2[0] * r[0]) + fmaf(wo2[3], r[3], wo2[2] * r[2]));

        // 4 shfl_down rounds: lanes 0 and 16 end with 16-lane sums.
#pragma unroll
        for (int off = 1; off <= 8; off <<= 1) {
            v  += __shfl_down_sync(0xffffffffu, v,  off);
            u  += __shfl_down_sync(0xffffffffu, u,  off);
            y0 += __shfl_down_sync(0xffffffffu, y0, off);
            y1 += __shfl_down_sync(0xffffffffu, y1, off);
            y2 += __shfl_down_sync(0xffffffffu, y2, off);
        }

        if ((lane & 15) == 0) {
            sp[buf][slot] = make_float2(v, u);
            // y partials: fire-and-forget STG, finalized by second kernel.
            float* yp = ypbase + (size_t)t * (OUTDIM * 8);
            yp[0]  = y0;
            yp[8]  = y1;
            yp[16] = y2;
        }
        __syncthreads();   // single barrier per step (double-buffered sp)

        // Cross-warp: 8 (v,u) pairs as 4 float4 broadcast loads + depth-3 tree.
        const float4* q = reinterpret_cast<const float4*>(sp[buf]);
        float4 q0 = q[0], q1 = q[1], q2 = q[2], q3 = q[3];
        s0 = ((q0.x + q0.z) + (q1.x + q1.z)) + ((q2.x + q2.z) + (q3.x + q3.z));
        s1 = ((q0.y + q0.w) + (q1.y + q1.w)) + ((q2.y + q2.w) + (q3.y + q3.w));
        buf ^= 1;
    }
}

__global__ void finalize_y_kernel(float* __restrict__ out)
{
    int i = blockIdx.x * blockDim.x + threadIdx.x;   // i in [0, B*T*OUT)
    if (i >= BATCH * TSTEPS * OUTDIM) return;
    const float4* p = reinterpret_cast<const float4*>(g_ypart + (size_t)i * 8);
    float4 a = p[0], c = p[1];
    float s = ((a.x + a.y) + (a.z + a.w)) + ((c.x + c.y) + (c.z + c.w));
    int o = i % OUTDIM;
    int t = (i / OUTDIM) % TSTEPS;
    int b = i / (OUTDIM * TSTEPS);
    out[(t * BATCH + b) * OUTDIM + o] = s;            // y: [T,B,OUT,1]
}

extern "C" void kernel_launch(void* const* d_in, const int* in_sizes, int n_in,
                              void* d_out, int out_size)
{
    const float* x    = (const float*)d_in[0];  // [1000,64,4,1]
    const float* Win  = (const float*)d_in[1];  // [512,4]
    const float* Wout = (const float*)d_in[2];  // [3,512]
    const float* pin  = (const float*)d_in[3];  // [512,2]
    const float* pout = (const float*)d_in[4];  // [512,2]
    const float* l    = (const float*)d_in[5];  // [2]

    rate_rnn_scan_kernel<<<BATCH, NTHR>>>(x, Win, Wout, pin, pout, l);

    int ny = BATCH * TSTEPS * OUTDIM;
    finalize_y_kernel<<<(ny + 255) / 256, 256>>>((float*)d_out);
}

// round 10
// speedup vs baseline: 1.0291x; 1.0291x over previous
#include <cuda_runtime.h>

// rate_RNN_mante: T=1000 sequential steps, B=64, IN=4, H=512, OUT=3.
// Wr = (l*pin) @ pout^T is rank-2 -> only two H-wide reductions (s0,s1) per
// step are on the critical path. One CTA per batch; 4 warps x 32 lanes x 4
// hidden units per thread.
//
// Critical-path discipline:
//   pre-barrier : mem update, tanh, po-products, v/u shuffles, STS  (nothing else)
//   post-barrier: LDS s-partials; y-products fill the LDS shadow; s-tree;
//                 y shuffles issued here overlap the NEXT step's compute;
//                 y partial STG is deferred one full step (chain long done).
// State kept pre-scaled by c=2*log2(e) so ex2.approx takes it directly.
// tanh = 1 - 2/(2^M + 1) via MUFU EX2 + RCP (abs err ~1e-7).

#define TSTEPS 1000
#define BATCH  64
#define HID    512
#define OUTDIM 3
#define NTHR   128          // 4 warps
#define UPT    4            // hidden units per thread

// y partial scratch: [B][T][OUT][8 partials]
__device__ float g_ypart[BATCH * TSTEPS * OUTDIM * 8];

__global__ __launch_bounds__(NTHR, 1)
void rate_rnn_scan_kernel(const float* __restrict__ x,
                          const float* __restrict__ Win,
                          const float* __restrict__ Wout,
                          const float* __restrict__ pin,
                          const float* __restrict__ pout,
                          const float* __restrict__ l)
{
    const int b    = blockIdx.x;
    const int tid  = threadIdx.x;
    const int lane = tid & 31;
    const int wid  = tid >> 5;
    const int half = lane >> 4;            // 0: lanes 0-15, 1: lanes 16-31
    const int slot = wid * 2 + half;       // 8 partial slots
    const bool writer = ((lane & 15) == 0);

    __shared__ float4 xs[TSTEPS];                 // staged input column (16 KB)
    __shared__ __align__(16) float2 sp[2][8];     // double-buffered s partials

    const float4* x4 = reinterpret_cast<const float4*>(x);  // x is [T,B,4,1]
    for (int t = tid; t < TSTEPS; t += NTHR)
        xs[t] = x4[t * BATCH + b];

    const float lm = 0.90483741803595952735f;     // exp(-dt/taum) = exp(-0.1)
    const float om = 1.0f - lm;
    const float cc = 2.88539008177792681472f;     // 2*log2(e); state M = cc*mem
    const float oc = om * cc;
    const float l0 = l[0], l1 = l[1];

    float4 wi[UPT];
    float  pi0[UPT], pi1[UPT], po0[UPT], po1[UPT];
    float  wo0[UPT], wo1[UPT], wo2[UPT];
    float  M[UPT];
#pragma unroll
    for (int k = 0; k < UPT; ++k) {
        int h = tid * UPT + k;
        float4 w = reinterpret_cast<const float4*>(Win)[h];
        wi[k] = make_float4(w.x * oc, w.y * oc, w.z * oc, w.w * oc);
        pi0[k] = pin[h * 2 + 0] * l0 * oc;
        pi1[k] = pin[h * 2 + 1] * l1 * oc;
        po0[k] = pout[h * 2 + 0];
        po1[k] = pout[h * 2 + 1];
        wo0[k] = Wout[h];
        wo1[k] = Wout[HID + h];
        wo2[k] = Wout[2 * HID + h];
        M[k]   = 0.0f;
    }

    float s0 = 0.0f, s1 = 0.0f;        // pout^T tanh(mem_{t-1}); zero at t=0
    float yc0 = 0.f, yc1 = 0.f, yc2 = 0.f;  // completed y partials of step t-1
    int buf = 0;

    float* ypbase = g_ypart + (size_t)b * TSTEPS * (OUTDIM * 8) + slot;

    __syncthreads();   // xs staged

    for (int t = 0; t < TSTEPS; ++t) {
        float4 xt = xs[t];
        float acc[UPT], r[UPT];

        // Off critical path: acc = lm*M + cc*om*(Win . x_t)
#pragma unroll
        for (int k = 0; k < UPT; ++k) {
            float iin = fmaf(wi[k].w, xt.w, fmaf(wi[k].z, xt.z,
                        fmaf(wi[k].y, xt.y, wi[k].x * xt.x)));
            acc[k] = fmaf(lm, M[k], iin);
        }
        // Critical chain: s -> M -> tanh  (M pre-scaled, ex2 takes it directly)
#pragma unroll
        for (int k = 0; k < UPT; ++k) {
            float m = fmaf(pi1[k], s1, fmaf(pi0[k], s0, acc[k]));
            M[k] = m;
            float e, rc;
            asm("ex2.approx.f32 %0, %1;" : "=f"(e)  : "f"(m));
            asm("rcp.approx.f32 %0, %1;" : "=f"(rc) : "f"(e + 1.0f));
            r[k] = fmaf(-2.0f, rc, 1.0f);
        }

        // Only the s-reductions run before the barrier.
        float v = fmaf(po0[1], r[1], po0[0] * r[0]) + fmaf(po0[3], r[3], po0[2] * r[2]);
        float u = fmaf(po1[1], r[1], po1[0] * r[0]) + fmaf(po1[3], r[3], po1[2] * r[2]);
#pragma unroll
        for (int off = 1; off <= 8; off <<= 1) {
            v += __shfl_down_sync(0xffffffffu, v, off);
            u += __shfl_down_sync(0xffffffffu, u, off);
        }
        if (writer) sp[buf][slot] = make_float2(v, u);

        __syncthreads();   // single barrier per step (double-buffered sp)

        // LDS of s partials; y products fill the 29-cycle LDS shadow.
        const float4* q = reinterpret_cast<const float4*>(sp[buf]);
        float4 q0 = q[0], q1 = q[1], q2 = q[2], q3 = q[3];

        float y0 = fmaf(wo0[1], r[1], wo0[0] * r[0]) + fmaf(wo0[3], r[3], wo0[2] * r[2]);
        float y1 = fmaf(wo1[1], r[1], wo1[0] * r[0]) + fmaf(wo1[3], r[3], wo1[2] * r[2]);
        float y2 = fmaf(wo2[1], r[1], wo2[0] * r[0]) + fmaf(wo2[3], r[3], wo2[2] * r[2]);

        s0 = ((q0.x + q0.z) + (q1.x + q1.z)) + ((q2.x + q2.z) + (q3.x + q3.z));
        s1 = ((q0.y + q0.w) + (q1.y + q1.w)) + ((q2.y + q2.w) + (q3.y + q3.w));

        // Flush step t-1's y partials (their shfl chain completed ~1 step ago).
        if (t > 0 && writer) {
            float* yp = ypbase + (size_t)(t - 1) * (OUTDIM * 8);
            yp[0]  = yc0;
            yp[8]  = yc1;
            yp[16] = yc2;
        }
        // Issue step t's y chains; they overlap the next step's compute.
#pragma unroll
        for (int off = 1; off <= 8; off <<= 1) {
            y0 += __shfl_down_sync(0xffffffffu, y0, off);
            y1 += __shfl_down_sync(0xffffffffu, y1, off);
            y2 += __shfl_down_sync(0xffffffffu, y2, off);
        }
        yc0 = y0; yc1 = y1; yc2 = y2;

        buf ^= 1;
    }
    if (writer) {   // final step's y partials
        float* yp = ypbase + (size_t)(TSTEPS - 1) * (OUTDIM * 8);
        yp[0]  = yc0;
        yp[8]  = yc1;
        yp[16] = yc2;
    }
}

__global__ void finalize_y_kernel(float* __restrict__ out)
{
    int i = blockIdx.x * blockDim.x + threadIdx.x;   // i in [0, B*T*OUT)
    if (i >= BATCH * TSTEPS * OUTDIM) return;
    const float4* p = reinterpret_cast<const float4*>(g_ypart + (size_t)i * 8);
    float4 a = p[0], c = p[1];
    float s = ((a.x + a.y) + (a.z + a.w)) + ((c.x + c.y) + (c.z + c.w));
    int o = i % OUTDIM;
    int t = (i / OUTDIM) % TSTEPS;
    int b = i / (OUTDIM * TSTEPS);
    out[(t * BATCH + b) * OUTDIM + o] = s;            // y: [T,B,OUT,1]
}

extern "C" void kernel_launch(void* const* d_in, const int* in_sizes, int n_in,
                              void* d_out, int out_size)
{
    const float* x    = (const float*)d_in[0];  // [1000,64,4,1]
    const float* Win  = (const float*)d_in[1];  // [512,4]
    const float* Wout = (const float*)d_in[2];  // [3,512]
    const float* pin  = (const float*)d_in[3];  // [512,2]
    const float* pout = (const float*)d_in[4];  // [512,2]
    const float* l    = (const float*)d_in[5];  // [2]

    rate_rnn_scan_kernel<<<BATCH, NTHR>>>(x, Win, Wout, pin, pout, l);

    int ny = BATCH * TSTEPS * OUTDIM;
    finalize_y_kernel<<<(ny + 255) / 256, 256>>>((float*)d_out);
}